// round 9
// baseline (speedup 1.0000x reference)
#include <cuda_runtime.h>
#include <cuda_bf16.h>
#include <cstdint>
#include <math.h>

#define BATCH 2
#define SEQ   2048
#define EMB   1024
#define HEADS 16
#define HDIM  64
#define NROWS (BATCH*SEQ)

// ---------------- scratch (__device__ globals; no allocs allowed) -----------
__device__ __nv_bfloat16 g_xh[NROWS*EMB], g_xl[NROWS*EMB];
__device__ __nv_bfloat16 g_ch[NROWS*EMB], g_cl[NROWS*EMB];
__device__ __nv_bfloat16 g_wh[4][EMB*EMB], g_wl[4][EMB*EMB];
__device__ __nv_bfloat16 g_qh[NROWS*EMB], g_ql[NROWS*EMB];
__device__ __nv_bfloat16 g_kh[NROWS*EMB], g_kl[NROWS*EMB];
__device__ __nv_bfloat16 g_vh[NROWS*EMB], g_vl[NROWS*EMB];

// ---------------- helpers ----------------------------------------------------
__device__ __forceinline__ uint32_t smem_u32(const void* p) {
    uint32_t a;
    asm("{ .reg .u64 t; cvta.to.shared.u64 t, %1; cvt.u32.u64 %0, t; }" : "=r"(a) : "l"(p));
    return a;
}
__device__ __forceinline__ void mma16816(float* c, const uint32_t* a,
                                         uint32_t b0, uint32_t b1) {
    asm volatile(
        "mma.sync.aligned.m16n8k16.row.col.f32.bf16.bf16.f32 "
        "{%0,%1,%2,%3}, {%4,%5,%6,%7}, {%8,%9}, {%0,%1,%2,%3};"
        : "+f"(c[0]), "+f"(c[1]), "+f"(c[2]), "+f"(c[3])
        : "r"(a[0]), "r"(a[1]), "r"(a[2]), "r"(a[3]), "r"(b0), "r"(b1));
}
__device__ __forceinline__ void ldsm4(uint32_t* r, uint32_t addr) {
    asm volatile("ldmatrix.sync.aligned.m8n8.x4.shared.b16 {%0,%1,%2,%3}, [%4];"
        : "=r"(r[0]), "=r"(r[1]), "=r"(r[2]), "=r"(r[3]) : "r"(addr));
}
__device__ __forceinline__ void ldsm4t(uint32_t& r0, uint32_t& r1,
                                       uint32_t& r2, uint32_t& r3, uint32_t addr) {
    asm volatile("ldmatrix.sync.aligned.m8n8.x4.trans.shared.b16 {%0,%1,%2,%3}, [%4];"
        : "=r"(r0), "=r"(r1), "=r"(r2), "=r"(r3) : "r"(addr));
}
__device__ __forceinline__ void cp16(uint32_t dst, const void* src) {
    asm volatile("cp.async.cg.shared.global [%0], [%1], 16;" :: "r"(dst), "l"(src) : "memory");
}
#define CP_COMMIT() asm volatile("cp.async.commit_group;" ::: "memory")
#define CP_WAIT1()  asm volatile("cp.async.wait_group 1;" ::: "memory")
#define CP_WAIT0()  asm volatile("cp.async.wait_group 0;" ::: "memory")

__device__ __forceinline__ uint32_t packbf(float lo, float hi) {
    __nv_bfloat162 t = __floats2bfloat162_rn(lo, hi);
    return *reinterpret_cast<uint32_t*>(&t);
}
__device__ __forceinline__ void store_split(__nv_bfloat16* oh, __nv_bfloat16* ol,
                                            size_t idx, float v0, float v1) {
    __nv_bfloat16 h0 = __float2bfloat16_rn(v0), h1 = __float2bfloat16_rn(v1);
    *(__nv_bfloat162*)(oh + idx) = __nv_bfloat162(h0, h1);
    *(__nv_bfloat162*)(ol + idx) = __nv_bfloat162(
        __float2bfloat16_rn(v0 - __bfloat162float(h0)),
        __float2bfloat16_rn(v1 - __bfloat162float(h1)));
}

// ---------------------------------------------------------------------------
// fused split: x (2^20 float4) + 4 weights (2^18 float4 each) in ONE launch
// ---------------------------------------------------------------------------
#define NX4 (NROWS*EMB/4)     // 1048576
#define NW4 (EMB*EMB/4)       // 262144 = 2^18

__global__ __launch_bounds__(256) void split_all(const float4* __restrict__ x,
                                                 const float4* __restrict__ w0,
                                                 const float4* __restrict__ w1,
                                                 const float4* __restrict__ w2,
                                                 const float4* __restrict__ w3,
                                                 __nv_bfloat162* __restrict__ xh,
                                                 __nv_bfloat162* __restrict__ xl,
                                                 __nv_bfloat162* __restrict__ wh,
                                                 __nv_bfloat162* __restrict__ wl) {
    int i = blockIdx.x * blockDim.x + threadIdx.x;
    const float4* src; __nv_bfloat162* oh; __nv_bfloat162* ol; int idx;
    if (i < NX4) {
        src = x; oh = xh; ol = xl; idx = i;
    } else {
        int j = i - NX4;
        int wsel = j >> 18;
        idx = j & (NW4 - 1);
        src = (wsel == 0) ? w0 : (wsel == 1) ? w1 : (wsel == 2) ? w2 : w3;
        oh = wh + (size_t)wsel * (EMB*EMB/2);
        ol = wl + (size_t)wsel * (EMB*EMB/2);
    }
    float4 a = src[idx];
    __nv_bfloat16 h0 = __float2bfloat16_rn(a.x);
    __nv_bfloat16 h1 = __float2bfloat16_rn(a.y);
    __nv_bfloat16 h2 = __float2bfloat16_rn(a.z);
    __nv_bfloat16 h3 = __float2bfloat16_rn(a.w);
    oh[idx*2+0] = __nv_bfloat162(h0, h1);
    oh[idx*2+1] = __nv_bfloat162(h2, h3);
    ol[idx*2+0] = __nv_bfloat162(__float2bfloat16_rn(a.x - __bfloat162float(h0)),
                                 __float2bfloat16_rn(a.y - __bfloat162float(h1)));
    ol[idx*2+1] = __nv_bfloat162(__float2bfloat16_rn(a.z - __bfloat162float(h2)),
                                 __float2bfloat16_rn(a.w - __bfloat162float(h3)));
}

// ---------------------------------------------------------------------------
// GEMM core: 128x128 CTA tile, 8 warps (4m x 2n), warp tile 32x64.
// k-chunk 64, cp.async double buffer, ldmatrix fragment loads, 3-pass split.
// ---------------------------------------------------------------------------
#define GP   72
#define GPB  144
#define GT_TILE  (128*GPB)
#define GT_STAGE (4*GT_TILE)
#define GT_SMEM  (2*GT_STAGE)

__device__ __forceinline__ void gemm_core(const __nv_bfloat16* __restrict__ Ah,
                                          const __nv_bfloat16* __restrict__ Al,
                                          const __nv_bfloat16* __restrict__ Bh,
                                          const __nv_bfloat16* __restrict__ Bl,
                                          uint32_t smb,
                                          int m0, int n0, float acc[2][8][4]) {
    const int tid = threadIdx.x;
    const int w = tid >> 5, lane = tid & 31;
    const int wm = w & 3, wn = w >> 2;

    const char* gsrc[4] = { (const char*)(Ah + (size_t)m0 * EMB),
                            (const char*)(Al + (size_t)m0 * EMB),
                            (const char*)(Bh + (size_t)n0 * EMB),
                            (const char*)(Bl + (size_t)n0 * EMB) };

    auto issue = [&](int kc, int stg) {
        uint32_t dstb = smb + stg * GT_STAGE;
        #pragma unroll
        for (int mX = 0; mX < 4; mX++) {
            #pragma unroll
            for (int j = 0; j < 4; j++) {
                int idx = tid + j * 256;
                int r = idx >> 3, c = idx & 7;
                cp16(dstb + mX*GT_TILE + r*GPB + c*16,
                     gsrc[mX] + kc*128 + (size_t)r*2048 + c*16);
            }
        }
        CP_COMMIT();
    };

    // ldmatrix per-lane fragment offset: rows 0-7 / 8-15 / 0-7(+16B) / 8-15(+16B)
    const uint32_t foff = (uint32_t)(((lane & 7) + ((lane >> 3) & 1)*8) * GPB + (lane >> 4)*16);

    issue(0, 0);
    for (int kc = 0; kc < 16; kc++) {
        int cur = kc & 1;
        if (kc < 15) { issue(kc + 1, cur ^ 1); CP_WAIT1(); }
        else         { CP_WAIT0(); }
        __syncthreads();

        uint32_t SAH = smb + cur*GT_STAGE;
        uint32_t SAL = SAH + GT_TILE;
        uint32_t SBH = SAH + 2*GT_TILE;
        uint32_t SBL = SAH + 3*GT_TILE;

        #pragma unroll
        for (int ks = 0; ks < 4; ks++) {
            uint32_t ah[2][4], al[2][4];
            #pragma unroll
            for (int mt = 0; mt < 2; mt++) {
                uint32_t ab = (uint32_t)((wm*32 + mt*16)*GPB + ks*32) + foff;
                ldsm4(ah[mt], SAH + ab);
                ldsm4(al[mt], SAL + ab);
            }
            #pragma unroll
            for (int ntp = 0; ntp < 4; ntp++) {
                uint32_t bb = (uint32_t)((wn*64 + ntp*16)*GPB + ks*32) + foff;
                uint32_t bh[4], bl[4];
                ldsm4(bh, SBH + bb);
                ldsm4(bl, SBL + bb);
                // tiles: r0=n0-7 k0-7, r1=n8-15 k0-7, r2=n0-7 k8-15, r3=n8-15 k8-15
                mma16816(acc[0][2*ntp],   ah[0], bh[0], bh[2]);
                mma16816(acc[0][2*ntp+1], ah[0], bh[1], bh[3]);
                mma16816(acc[1][2*ntp],   ah[1], bh[0], bh[2]);
                mma16816(acc[1][2*ntp+1], ah[1], bh[1], bh[3]);
                mma16816(acc[0][2*ntp],   al[0], bh[0], bh[2]);
                mma16816(acc[0][2*ntp+1], al[0], bh[1], bh[3]);
                mma16816(acc[1][2*ntp],   al[1], bh[0], bh[2]);
                mma16816(acc[1][2*ntp+1], al[1], bh[1], bh[3]);
                mma16816(acc[0][2*ntp],   ah[0], bl[0], bl[2]);
                mma16816(acc[0][2*ntp+1], ah[0], bl[1], bl[3]);
                mma16816(acc[1][2*ntp],   ah[1], bl[0], bl[2]);
                mma16816(acc[1][2*ntp+1], ah[1], bl[1], bl[3]);
            }
        }
        __syncthreads();
    }
}

// ---------------------------------------------------------------------------
// Fused QKV projection: z=0 Q(rope+split), z=1 K(rope+split), z=2 V(split)
// ---------------------------------------------------------------------------
__global__ __launch_bounds__(256) void gemm_qkv(const __nv_bfloat16* __restrict__ xh,
                                                const __nv_bfloat16* __restrict__ xl,
                                                const __nv_bfloat16* __restrict__ wh,
                                                const __nv_bfloat16* __restrict__ wl,
                                                __nv_bfloat16* __restrict__ qh,
                                                __nv_bfloat16* __restrict__ ql,
                                                __nv_bfloat16* __restrict__ kh,
                                                __nv_bfloat16* __restrict__ kl,
                                                __nv_bfloat16* __restrict__ vh,
                                                __nv_bfloat16* __restrict__ vl) {
    extern __shared__ char sm[];
    const int z = blockIdx.z;
    const int n0 = blockIdx.x * 128, m0 = blockIdx.y * 128;
    float acc[2][8][4] = {};
    gemm_core(xh, xl, wh + (size_t)z*EMB*EMB, wl + (size_t)z*EMB*EMB,
              smem_u32(sm), m0, n0, acc);

    const int tid = threadIdx.x;
    const int w = tid >> 5, lane = tid & 31, g = lane >> 2, t4 = lane & 3;
    const int wm = w & 3, wn = w >> 2;

    __nv_bfloat16* oh = (z == 0) ? qh : (z == 1) ? kh : vh;
    __nv_bfloat16* ol = (z == 0) ? ql : (z == 1) ? kl : vl;

    if (z < 2) {
        #pragma unroll
        for (int mt = 0; mt < 2; mt++) {
            int rbase = m0 + wm*32 + mt*16 + g;
            #pragma unroll
            for (int jr = 0; jr < 2; jr++) {
                int row = rbase + jr*8;
                int s = row & (SEQ - 1);
                #pragma unroll
                for (int nt = 0; nt < 4; nt++) {
                    int dbase = nt*8 + t4*2;
                    float o0[2], o1[2];
                    #pragma unroll
                    for (int jc = 0; jc < 2; jc++) {
                        int d = dbase + jc;
                        float inv = exp2f(-(float)(2*d) * (13.287712379549449f / 64.0f));
                        float sn, cs;
                        sincosf((float)s * inv, &sn, &cs);
                        float x1 = acc[mt][nt][jr*2+jc];
                        float x2 = acc[mt][nt+4][jr*2+jc];
                        o0[jc] = x1*cs - x2*sn;
                        o1[jc] = x2*cs + x1*sn;
                    }
                    size_t base = (size_t)row * EMB + n0 + wn*64 + dbase;
                    store_split(oh, ol, base,      o0[0], o0[1]);
                    store_split(oh, ol, base + 32, o1[0], o1[1]);
                }
            }
        }
    } else {
        #pragma unroll
        for (int mt = 0; mt < 2; mt++) {
            int row0 = m0 + wm*32 + mt*16 + g;
            #pragma unroll
            for (int nt = 0; nt < 8; nt++) {
                size_t base = (size_t)row0 * EMB + n0 + wn*64 + nt*8 + t4*2;
                store_split(oh, ol, base,          acc[mt][nt][0], acc[mt][nt][1]);
                store_split(oh, ol, base + 8*EMB,  acc[mt][nt][2], acc[mt][nt][3]);
            }
        }
    }
}

// ---------------------------------------------------------------------------
// Output projection
// ---------------------------------------------------------------------------
__global__ __launch_bounds__(256) void gemm_o(const __nv_bfloat16* __restrict__ Ah,
                                              const __nv_bfloat16* __restrict__ Al,
                                              const __nv_bfloat16* __restrict__ Bh,
                                              const __nv_bfloat16* __restrict__ Bl,
                                              float* __restrict__ C) {
    extern __shared__ char sm[];
    const int n0 = blockIdx.x * 128, m0 = blockIdx.y * 128;
    float acc[2][8][4] = {};
    gemm_core(Ah, Al, Bh, Bl, smem_u32(sm), m0, n0, acc);

    const int tid = threadIdx.x;
    const int w = tid >> 5, lane = tid & 31, g = lane >> 2, t4 = lane & 3;
    const int wm = w & 3, wn = w >> 2;
    #pragma unroll
    for (int mt = 0; mt < 2; mt++) {
        int row = m0 + wm*32 + mt*16 + g;
        #pragma unroll
        for (int nt = 0; nt < 8; nt++) {
            float* p0 = C + (size_t)row * EMB + n0 + wn*64 + nt*8 + t4*2;
            *(float2*)p0 = make_float2(acc[mt][nt][0], acc[mt][nt][1]);
            *(float2*)(p0 + 8*EMB) = make_float2(acc[mt][nt][2], acc[mt][nt][3]);
        }
    }
}

// ---------------------------------------------------------------------------
// mma.sync flash attention, cp.async double-buffered, ldmatrix everywhere.
// ---------------------------------------------------------------------------
#define AT_TILE  (64*GPB)
#define AT_STAGE (4*AT_TILE)
#define ATTN_SMEM (2*AT_STAGE)

__global__ __launch_bounds__(256) void attn_mma(const __nv_bfloat16* __restrict__ qh,
                                                const __nv_bfloat16* __restrict__ ql,
                                                const __nv_bfloat16* __restrict__ khg,
                                                const __nv_bfloat16* __restrict__ klg,
                                                const __nv_bfloat16* __restrict__ vhg,
                                                const __nv_bfloat16* __restrict__ vlg,
                                                __nv_bfloat16* __restrict__ ch,
                                                __nv_bfloat16* __restrict__ cl) {
    extern __shared__ char sm[];
    const uint32_t smb = smem_u32(sm);

    const int tid = threadIdx.x;
    const int w = tid >> 5, lane = tid & 31, g = lane >> 2, t4 = lane & 3;
    const int qt = gridDim.x - 1 - blockIdx.x;   // longest CTAs first
    const int h = blockIdx.y, b = blockIdx.z;

    const int row_base = qt*128 + w*16;
    const int row0 = row_base + g;
    const int row1 = row0 + 8;
    const size_t hoff = (size_t)h * HDIM;

    uint32_t aqh[4][4], aql[4][4];
    {
        size_t qb = ((size_t)(b*SEQ) + row0) * EMB + hoff;
        #pragma unroll
        for (int ks = 0; ks < 4; ks++) {
            const __nv_bfloat16* p = qh + qb + ks*16 + t4*2;
            aqh[ks][0] = *(const uint32_t*)p;
            aqh[ks][1] = *(const uint32_t*)(p + 8*EMB);
            aqh[ks][2] = *(const uint32_t*)(p + 8);
            aqh[ks][3] = *(const uint32_t*)(p + 8*EMB + 8);
            const __nv_bfloat16* q2 = ql + qb + ks*16 + t4*2;
            aql[ks][0] = *(const uint32_t*)q2;
            aql[ks][1] = *(const uint32_t*)(q2 + 8*EMB);
            aql[ks][2] = *(const uint32_t*)(q2 + 8);
            aql[ks][3] = *(const uint32_t*)(q2 + 8*EMB + 8);
        }
    }

    auto issue = [&](int kt, int stg) {
        size_t kvb = ((size_t)(b*SEQ) + kt*64) * EMB + hoff;
        const char* srcs[4] = { (const char*)(khg + kvb), (const char*)(klg + kvb),
                                (const char*)(vhg + kvb), (const char*)(vlg + kvb) };
        uint32_t dstb = smb + stg * AT_STAGE;
        #pragma unroll
        for (int t = 0; t < 4; t++) {
            #pragma unroll
            for (int j = 0; j < 2; j++) {
                int idx = tid + j*256;
                int r = idx >> 3, c = idx & 7;
                cp16(dstb + t*AT_TILE + r*GPB + c*16, srcs[t] + (size_t)r*2048 + c*16);
            }
        }
        CP_COMMIT();
    };

    float accO[8][4] = {};
    float m0 = -1e30f, m1 = -1e30f, l0 = 0.0f, l1 = 0.0f;
    const float Cs = 0.125f * 1.4426950408889634f;

    const int ntiles = 2*qt + 2;
    const uint32_t foff = (uint32_t)(((lane & 7) + ((lane >> 3) & 1)*8) * GPB + (lane >> 4)*16);

    issue(0, 0);
    for (int kt = 0; kt < ntiles; kt++) {
        int cur = kt & 1;
        if (kt + 1 < ntiles) { issue(kt + 1, cur ^ 1); CP_WAIT1(); }
        else                 { CP_WAIT0(); }
        __syncthreads();

        uint32_t KH = smb + cur*AT_STAGE;
        uint32_t KL = KH + AT_TILE;
        const uint32_t vhb = KH + 2*AT_TILE + foff;
        const uint32_t vlb = vhb + AT_TILE;

        if (kt*64 <= row_base + 15) {
            // ---- S = Q K^T (3-pass, ldmatrix K-frags) ----
            float s[8][4] = {};
            #pragma unroll
            for (int ks = 0; ks < 4; ks++) {
                #pragma unroll
                for (int ntp = 0; ntp < 4; ntp++) {
                    uint32_t kb = (uint32_t)(ntp*16*GPB + ks*32) + foff;
                    uint32_t bh[4], bl[4];
                    ldsm4(bh, KH + kb);
                    ldsm4(bl, KL + kb);
                    mma16816(s[2*ntp],   aqh[ks], bh[0], bh[2]);
                    mma16816(s[2*ntp+1], aqh[ks], bh[1], bh[3]);
                    mma16816(s[2*ntp],   aql[ks], bh[0], bh[2]);
                    mma16816(s[2*ntp+1], aql[ks], bh[1], bh[3]);
                    mma16816(s[2*ntp],   aqh[ks], bl[0], bl[2]);
                    mma16816(s[2*ntp+1], aqh[ks], bl[1], bl[3]);
                }
            }
            // ---- mask + scale ----
            #pragma unroll
            for (int nt = 0; nt < 8; nt++) {
                int colb = kt*64 + nt*8 + t4*2;
                s[nt][0] = (colb     > row0) ? -3e28f : s[nt][0]*Cs;
                s[nt][1] = (colb + 1 > row0) ? -3e28f : s[nt][1]*Cs;
                s[nt][2] = (colb     > row1) ? -3e28f : s[nt][2]*Cs;
                s[nt][3] = (colb + 1 > row1) ? -3e28f : s[nt][3]*Cs;
            }
            // ---- row max ----
            float rm0 = -3e28f, rm1 = -3e28f;
            #pragma unroll
            for (int nt = 0; nt < 8; nt++) {
                rm0 = fmaxf(rm0, fmaxf(s[nt][0], s[nt][1]));
                rm1 = fmaxf(rm1, fmaxf(s[nt][2], s[nt][3]));
            }
            rm0 = fmaxf(rm0, __shfl_xor_sync(0xffffffffu, rm0, 1));
            rm0 = fmaxf(rm0, __shfl_xor_sync(0xffffffffu, rm0, 2));
            rm1 = fmaxf(rm1, __shfl_xor_sync(0xffffffffu, rm1, 1));
            rm1 = fmaxf(rm1, __shfl_xor_sync(0xffffffffu, rm1, 2));

            float mn0 = fmaxf(m0, rm0), mn1 = fmaxf(m1, rm1);
            float alpha0 = exp2f(m0 - mn0), alpha1 = exp2f(m1 - mn1);
            m0 = mn0; m1 = mn1;

            float sum0 = 0.0f, sum1 = 0.0f;
            uint32_t aph[4][4], apl[4][4];
            #pragma unroll
            for (int nt = 0; nt < 8; nt++) {
                float p0 = exp2f(s[nt][0] - m0);
                float p1 = exp2f(s[nt][1] - m0);
                float p2 = exp2f(s[nt][2] - m1);
                float p3 = exp2f(s[nt][3] - m1);
                sum0 += p0 + p1;  sum1 += p2 + p3;
                __nv_bfloat16 h0 = __float2bfloat16_rn(p0), h1b = __float2bfloat16_rn(p1);
                __nv_bfloat16 h2 = __float2bfloat16_rn(p2), h3b = __float2bfloat16_rn(p3);
                float r0 = p0 - __bfloat162float(h0), r1 = p1 - __bfloat162float(h1b);
                float r2 = p2 - __bfloat162float(h2), r3 = p3 - __bfloat162float(h3b);
                int kc = nt >> 1, odd = nt & 1;
                __nv_bfloat162 th01(h0, h1b), th23(h2, h3b);
                aph[kc][odd ? 2 : 0] = *(uint32_t*)&th01;
                aph[kc][odd ? 3 : 1] = *(uint32_t*)&th23;
                apl[kc][odd ? 2 : 0] = packbf(r0, r1);
                apl[kc][odd ? 3 : 1] = packbf(r2, r3);
            }
            sum0 += __shfl_xor_sync(0xffffffffu, sum0, 1);
            sum0 += __shfl_xor_sync(0xffffffffu, sum0, 2);
            sum1 += __shfl_xor_sync(0xffffffffu, sum1, 1);
            sum1 += __shfl_xor_sync(0xffffffffu, sum1, 2);
            l0 = l0 * alpha0 + sum0;
            l1 = l1 * alpha1 + sum1;

            #pragma unroll
            for (int nt = 0; nt < 8; nt++) {
                accO[nt][0] *= alpha0; accO[nt][1] *= alpha0;
                accO[nt][2] *= alpha1; accO[nt][3] *= alpha1;
            }
            // ---- O += P V (3-pass), V via ldmatrix.trans ----
            #pragma unroll
            for (int ks = 0; ks < 4; ks++) {
                #pragma unroll
                for (int ntp = 0; ntp < 4; ntp++) {
                    uint32_t r0, r1, r2, r3;
                    ldsm4t(r0, r1, r2, r3, vhb + ks*16*GPB + ntp*32);
                    mma16816(accO[2*ntp],   aph[ks], r0, r1);
                    mma16816(accO[2*ntp+1], aph[ks], r2, r3);
                    mma16816(accO[2*ntp],   apl[ks], r0, r1);
                    mma16816(accO[2*ntp+1], apl[ks], r2, r3);
                    ldsm4t(r0, r1, r2, r3, vlb + ks*16*GPB + ntp*32);
                    mma16816(accO[2*ntp],   aph[ks], r0, r1);
                    mma16816(accO[2*ntp+1], aph[ks], r2, r3);
                }
            }
        }
        __syncthreads();
    }

    float inv0 = 1.0f / l0, inv1 = 1.0f / l1;
    size_t ob = ((size_t)(b*SEQ) + row0) * EMB + hoff;
    #pragma unroll
    for (int nt = 0; nt < 8; nt++) {
        store_split(ch, cl, ob + nt*8 + t4*2,          accO[nt][0]*inv0, accO[nt][1]*inv0);
        store_split(ch, cl, ob + 8*EMB + nt*8 + t4*2,  accO[nt][2]*inv1, accO[nt][3]*inv1);
    }
}

// ---------------------------------------------------------------------------
extern "C" void kernel_launch(void* const* d_in, const int* in_sizes, int n_in,
                              void* d_out, int out_size) {
    const float* x  = (const float*)d_in[0];
    const float* Wq = (const float*)d_in[1];
    const float* Wk = (const float*)d_in[2];
    const float* Wv = (const float*)d_in[3];
    const float* Wo = (const float*)d_in[4];
    float* out = (float*)d_out;

    __nv_bfloat16 *xh, *xl, *ch, *cl, *wh, *wl;
    __nv_bfloat16 *qhp, *qlp, *khp, *klp, *vhp, *vlp;
    cudaGetSymbolAddress((void**)&xh, g_xh);
    cudaGetSymbolAddress((void**)&xl, g_xl);
    cudaGetSymbolAddress((void**)&ch, g_ch);
    cudaGetSymbolAddress((void**)&cl, g_cl);
    cudaGetSymbolAddress((void**)&wh, g_wh);
    cudaGetSymbolAddress((void**)&wl, g_wl);
    cudaGetSymbolAddress((void**)&qhp, g_qh);
    cudaGetSymbolAddress((void**)&qlp, g_ql);
    cudaGetSymbolAddress((void**)&khp, g_kh);
    cudaGetSymbolAddress((void**)&klp, g_kl);
    cudaGetSymbolAddress((void**)&vhp, g_vh);
    cudaGetSymbolAddress((void**)&vlp, g_vl);

    cudaFuncSetAttribute(gemm_qkv, cudaFuncAttributeMaxDynamicSharedMemorySize, GT_SMEM);
    cudaFuncSetAttribute(gemm_o,   cudaFuncAttributeMaxDynamicSharedMemorySize, GT_SMEM);
    cudaFuncSetAttribute(attn_mma, cudaFuncAttributeMaxDynamicSharedMemorySize, ATTN_SMEM);

    split_all<<<(NX4 + 4*NW4) / 256, 256>>>((const float4*)x,
        (const float4*)Wq, (const float4*)Wk, (const float4*)Wv, (const float4*)Wo,
        (__nv_bfloat162*)xh, (__nv_bfloat162*)xl,
        (__nv_bfloat162*)wh, (__nv_bfloat162*)wl);

    gemm_qkv<<<dim3(EMB/128, NROWS/128, 3), 256, GT_SMEM>>>(
        xh, xl, wh, wl, qhp, qlp, khp, klp, vhp, vlp);

    attn_mma<<<dim3(SEQ/128, HEADS, BATCH), 256, ATTN_SMEM>>>(
        qhp, qlp, khp, klp, vhp, vlp, ch, cl);

    gemm_o<<<dim3(EMB/128, NROWS/128), 256, GT_SMEM>>>(
        ch, cl, wh + 3*(size_t)EMB*EMB, wl + 3*(size_t)EMB*EMB, out);
}